// round 10
// baseline (speedup 1.0000x reference)
#include <cuda_runtime.h>

// FAC (per-pixel dynamic 3x3 filter) + LeakyReLU(0.2)
// feature: [8,64,128,128] f32; filters: [8,576,128,128] f32 (tap kh*3+kw minor)
//
// DRAM-bound at the 335 MB traffic floor (filters 302 MB read-once + out
// 33.5 MB; feature is L2-resident). R5/R7 established concurrency-invariance
// at ~85% DRAM. R9 = R5 code with block=1024 (__launch_bounds__(1024,2),
// reg budget still 32, occupancy unchanged at 2048 thr/SM): each block now
// streams 16 KB contiguous per tap plane instead of 4 KB -> 4x fewer DRAM
// stream switches per byte, probing row-buffer locality as the last lever.

#define HW 16384      // 128*128
#define W  128
#define H  128

__device__ __forceinline__ float4 ldcs4(const float* p) {
    float4 v;
    asm volatile("ld.global.cs.v4.f32 {%0,%1,%2,%3}, [%4];"
                 : "=f"(v.x), "=f"(v.y), "=f"(v.z), "=f"(v.w)
                 : "l"(p));
    return v;
}

__device__ __forceinline__ void stcs4(float* p, float4 v) {
    asm volatile("st.global.cs.v4.f32 [%0], {%1,%2,%3,%4};"
                 :: "l"(p), "f"(v.x), "f"(v.y), "f"(v.z), "f"(v.w)
                 : "memory");
}

__global__ __launch_bounds__(1024, 2)
void fac_leaky_kernel(const float* __restrict__ feat,
                      const float* __restrict__ filt,
                      float* __restrict__ out)
{
    // vec index over N*C*H*(W/4) = 2,097,152 ; lane == wv (warp spans one row)
    int idx = blockIdx.x * blockDim.x + threadIdx.x;

    int lane = idx & 31;            // W/4 group
    int h  = (idx >> 5) & 127;
    int nc = idx >> 12;             // n*64 + c
    int w0 = lane << 2;

    const float* fb = feat + (size_t)nc * HW;
    const float* pb = filt + (size_t)nc * 9 * HW + h * W + w0;

    float acc0 = 0.f, acc1 = 0.f, acc2 = 0.f, acc3 = 0.f;

    #pragma unroll
    for (int kh = 0; kh < 3; ++kh) {
        const float* tap = pb + kh * 3 * HW;
        float4 t0 = ldcs4(tap);
        float4 t1 = ldcs4(tap + HW);
        float4 t2 = ldcs4(tap + 2 * HW);

        int hh = h + kh - 1;
        float4 mid;
        if (hh >= 0 && hh < H) {
            mid = *reinterpret_cast<const float4*>(fb + hh * W + w0);
        } else {
            mid = make_float4(0.f, 0.f, 0.f, 0.f);
        }
        float f0 = __shfl_up_sync(0xffffffffu,   mid.w, 1);
        float f5 = __shfl_down_sync(0xffffffffu, mid.x, 1);
        if (lane == 0)  f0 = 0.f;
        if (lane == 31) f5 = 0.f;

        // kw = 0 : window offset [0..3]
        acc0 = fmaf(t0.x, f0,    acc0);
        acc1 = fmaf(t0.y, mid.x, acc1);
        acc2 = fmaf(t0.z, mid.y, acc2);
        acc3 = fmaf(t0.w, mid.z, acc3);
        // kw = 1 : offset [1..4]
        acc0 = fmaf(t1.x, mid.x, acc0);
        acc1 = fmaf(t1.y, mid.y, acc1);
        acc2 = fmaf(t1.z, mid.z, acc2);
        acc3 = fmaf(t1.w, mid.w, acc3);
        // kw = 2 : offset [2..5]
        acc0 = fmaf(t2.x, mid.y, acc0);
        acc1 = fmaf(t2.y, mid.z, acc1);
        acc2 = fmaf(t2.z, mid.w, acc2);
        acc3 = fmaf(t2.w, f5,    acc3);
    }

    float4 o;
    o.x = acc0 >= 0.f ? acc0 : 0.2f * acc0;
    o.y = acc1 >= 0.f ? acc1 : 0.2f * acc1;
    o.z = acc2 >= 0.f ? acc2 : 0.2f * acc2;
    o.w = acc3 >= 0.f ? acc3 : 0.2f * acc3;

    stcs4(out + (size_t)nc * HW + h * W + w0, o);
}

extern "C" void kernel_launch(void* const* d_in, const int* in_sizes, int n_in,
                              void* d_out, int out_size)
{
    const float* feature = (const float*)d_in[0];   // 8*64*128*128
    const float* filters = (const float*)d_in[1];   // 8*576*128*128
    float* out = (float*)d_out;

    const int total_vec = 8 * 64 * 128 * (128 / 4); // 2,097,152
    const int threads = 1024;
    const int blocks = total_vec / threads;         // 2048

    fac_leaky_kernel<<<blocks, threads>>>(feature, filters, out);
}